// round 2
// baseline (speedup 1.0000x reference)
#include <cuda_runtime.h>
#include <math.h>

// ---------------------------------------------------------------------------
// FCOS head: 5 levels, cls/box towers (4x [conv3x3 256->256 + GN(32) + ReLU]),
// heads: logits(80), ctr(1) from cls tower; reg(4)=exp(scale*conv) from box
// tower. Output: concat([logits, reg, ctr], ch).reshape(B,-1) per level,
// concatenated over levels, followed by FCOS locations [sumHW, 2].
//
// Strategy: spatially padded scratch buffers (zero borders -> no bounds checks
// in the GEMM), implicit-GEMM conv3x3 with 128x128x8 tiles, 8x8 microtile,
// double-buffered smem. Separate GN-stats / GN-apply+ReLU kernels.
// ---------------------------------------------------------------------------

#define BATCH 8
#define CIN 256
#define KDIM 2304           // 256*9

// Padded scratch: level 0 is largest: 8*256*102*154 floats = ~128.7 MB each.
__device__ float g_bufA[(size_t)BATCH * CIN * 102 * 154];
__device__ float g_bufB[(size_t)BATCH * CIN * 102 * 154];
__device__ float g_mean[BATCH * 32];
__device__ float g_rstd[BATCH * 32];

#define BM 128
#define BN 128
#define BK 8

// ---------------------------------------------------------------------------
// Implicit-GEMM conv3x3 (stride 1, pad 1) over a spatially padded input.
//   Y[m, p] = sum_k W[m, k] * X[k, p],  k = ci*9 + ky*3 + kx
//   X[k, p] = Xpad[b*256*HpWp + ci*HpWp + (y+ky)*Wp + (x+kx)],  p=(b,y,x)
// mode 0: write padded scratch interior (+bias)
// mode 1: write d_out at concat layout (+bias, optional exp(scale*x))
// ---------------------------------------------------------------------------
__global__ __launch_bounds__(256) void conv_gemm_kernel(
    const float* __restrict__ Wt,     // [M, 2304] row-major
    const float* __restrict__ bias,   // [M]
    const float* __restrict__ Xp,     // padded input
    float* __restrict__ Yp,           // padded output (mode 0)
    float* __restrict__ Yout,         // d_out (mode 1)
    int M, int H, int W,
    int mode, long out_boff, long lvl_off, int chan_off,
    const float* __restrict__ scales, int lvl, int do_exp)
{
    const int Hp = H + 2, Wp = W + 2;
    const int HW = H * W;
    const int HpWp = Hp * Wp;
    const int N = BATCH * HW;
    const int n0 = blockIdx.x * BN;
    const int m0 = blockIdx.y * BM;
    const int tid = threadIdx.x;

    __shared__ float As[2][BK][BM];   // 8 KB
    __shared__ float Bs[2][BK][BN];   // 8 KB
    __shared__ int   sbase[BN];

    // Per-column base offsets into the padded input.
    if (tid < BN) {
        int p = n0 + tid;
        int pp = (p < N) ? p : 0;     // clamp: loads stay in-bounds, result discarded
        int b = pp / HW; int r = pp - b * HW;
        int y = r / W;   int x = r - y * W;
        sbase[tid] = b * CIN * HpWp + y * Wp + x;
    }
    __syncthreads();

    // A-tile loader: thread t loads one float4 of W; rows 0..127, 2 threads/row.
    const int ar = tid >> 1;
    const int ac = (tid & 1) * 4;
    const bool amv = (m0 + ar) < M;
    const float* wrow = Wt + (long)(m0 + ar) * KDIM;

    // B-tile loader: thread t owns column bc, 4 k-rows starting at br0.
    const int bc  = tid & 127;
    const int br0 = (tid >> 7) * 4;   // 0 or 4
    const int bp  = sbase[bc];

    const int nIter = KDIM / BK;      // 288

    float4 av;
    float  bv[4];

    // Prologue: load tile 0 into buffer 0.
    av = amv ? *(const float4*)(wrow + ac) : make_float4(0.f, 0.f, 0.f, 0.f);
#pragma unroll
    for (int i = 0; i < 4; i++) {
        int k  = br0 + i;
        int ci = k / 9; int r9 = k - ci * 9;
        int ky = r9 / 3; int kx = r9 - ky * 3;
        bv[i] = Xp[bp + ci * HpWp + ky * Wp + kx];
    }
    As[0][ac + 0][ar] = av.x; As[0][ac + 1][ar] = av.y;
    As[0][ac + 2][ar] = av.z; As[0][ac + 3][ar] = av.w;
#pragma unroll
    for (int i = 0; i < 4; i++) Bs[0][br0 + i][bc] = bv[i];
    __syncthreads();

    // Compute mapping: 16x16 threads, 8x8 microtile.
    const int ty = tid >> 4;
    const int tx = tid & 15;

    float acc[8][8];
#pragma unroll
    for (int i = 0; i < 8; i++)
#pragma unroll
        for (int j = 0; j < 8; j++) acc[i][j] = 0.f;

    for (int it = 0; it < nIter; ++it) {
        const int buf = it & 1;

        // Prefetch next tile into registers while computing on current buffer.
        if (it + 1 < nIter) {
            const int k0 = (it + 1) * BK;
            av = amv ? *(const float4*)(wrow + k0 + ac)
                     : make_float4(0.f, 0.f, 0.f, 0.f);
#pragma unroll
            for (int i = 0; i < 4; i++) {
                int k  = k0 + br0 + i;
                int ci = k / 9; int r9 = k - ci * 9;
                int ky = r9 / 3; int kx = r9 - ky * 3;
                bv[i] = Xp[bp + ci * HpWp + ky * Wp + kx];
            }
        }

#pragma unroll
        for (int kk = 0; kk < BK; kk++) {
            float a[8], b[8];
            *(float4*)&a[0] = *(const float4*)&As[buf][kk][ty * 8];
            *(float4*)&a[4] = *(const float4*)&As[buf][kk][ty * 8 + 4];
            *(float4*)&b[0] = *(const float4*)&Bs[buf][kk][tx * 8];
            *(float4*)&b[4] = *(const float4*)&Bs[buf][kk][tx * 8 + 4];
#pragma unroll
            for (int i = 0; i < 8; i++)
#pragma unroll
                for (int j = 0; j < 8; j++)
                    acc[i][j] += a[i] * b[j];
        }

        if (it + 1 < nIter) {
            const int nb = buf ^ 1;
            As[nb][ac + 0][ar] = av.x; As[nb][ac + 1][ar] = av.y;
            As[nb][ac + 2][ar] = av.z; As[nb][ac + 3][ar] = av.w;
#pragma unroll
            for (int i = 0; i < 4; i++) Bs[nb][br0 + i][bc] = bv[i];
        }
        __syncthreads();
    }

    // Epilogue.
    int pb[8], pyy[8], pxx[8];
    bool pv[8];
#pragma unroll
    for (int j = 0; j < 8; j++) {
        int p = n0 + tx * 8 + j;
        pv[j] = (p < N);
        int pp = pv[j] ? p : 0;
        int b = pp / HW; int r = pp - b * HW;
        int y = r / W;   int x = r - y * W;
        pb[j] = b; pyy[j] = y; pxx[j] = x;
    }
    float sc = 1.f;
    if (do_exp) sc = scales[lvl];

#pragma unroll
    for (int i = 0; i < 8; i++) {
        int m = m0 + ty * 8 + i;
        if (m >= M) continue;
        float bvs = bias[m];
#pragma unroll
        for (int j = 0; j < 8; j++) {
            if (!pv[j]) continue;
            float v = acc[i][j] + bvs;
            if (mode == 0) {
                Yp[((long)(pb[j] * CIN + m) * Hp + pyy[j] + 1) * Wp + (pxx[j] + 1)] = v;
            } else {
                if (do_exp) v = expf(sc * v);
                Yout[(long)pb[j] * out_boff + lvl_off +
                     (long)(chan_off + m) * HW + pyy[j] * W + pxx[j]] = v;
            }
        }
    }
}

// ---------------------------------------------------------------------------
// GroupNorm statistics: one block per (batch, group); reduce 8 channels x HW.
// ---------------------------------------------------------------------------
__global__ __launch_bounds__(256) void gn_stats_kernel(
    const float* __restrict__ Xp, int H, int W)
{
    const int b = blockIdx.x >> 5;
    const int g = blockIdx.x & 31;
    const int Hp = H + 2, Wp = W + 2;
    const int HW = H * W;
    const int HpWp = Hp * Wp;
    const long base = ((long)b * CIN + g * 8) * HpWp;
    const int cnt = 8 * HW;

    float s = 0.f, s2 = 0.f;
    for (int i = threadIdx.x; i < cnt; i += 256) {
        int cc = i / HW; int r = i - cc * HW;
        int y = r / W;   int x = r - y * W;
        float v = Xp[base + cc * HpWp + (y + 1) * Wp + x + 1];
        s += v; s2 += v * v;
    }
    __shared__ float ss[256], ss2[256];
    ss[threadIdx.x] = s; ss2[threadIdx.x] = s2;
    __syncthreads();
    for (int o = 128; o > 0; o >>= 1) {
        if (threadIdx.x < o) {
            ss[threadIdx.x]  += ss[threadIdx.x + o];
            ss2[threadIdx.x] += ss2[threadIdx.x + o];
        }
        __syncthreads();
    }
    if (threadIdx.x == 0) {
        float mean = ss[0] / cnt;
        float var  = ss2[0] / cnt - mean * mean;
        g_mean[blockIdx.x] = mean;
        g_rstd[blockIdx.x] = rsqrtf(var + 1e-5f);
    }
}

// ---------------------------------------------------------------------------
// GN apply + ReLU, padded interior -> padded interior (other buffer).
// ---------------------------------------------------------------------------
__global__ __launch_bounds__(256) void gn_apply_relu_kernel(
    const float* __restrict__ src, float* __restrict__ dst,
    const float* __restrict__ gamma, const float* __restrict__ beta,
    int H, int W)
{
    const int HW = H * W;
    const int total = BATCH * CIN * HW;
    int idx = blockIdx.x * blockDim.x + threadIdx.x;
    if (idx >= total) return;
    int bc = idx / HW; int r = idx - bc * HW;
    int b = bc >> 8;   int c = bc & 255;
    int y = r / W;     int x = r - y * W;
    const int Hp = H + 2, Wp = W + 2;
    long addr = ((long)bc * Hp + y + 1) * Wp + x + 1;
    int bg = b * 32 + (c >> 3);
    float v = (src[addr] - g_mean[bg]) * g_rstd[bg] * gamma[c] + beta[c];
    dst[addr] = v > 0.f ? v : 0.f;
}

// ---------------------------------------------------------------------------
// Copy unpadded feature into padded buffer interior.
// ---------------------------------------------------------------------------
__global__ __launch_bounds__(256) void pad_copy_kernel(
    const float* __restrict__ feat, float* __restrict__ Xp, int H, int W)
{
    const int HW = H * W;
    const int total = BATCH * CIN * HW;
    int idx = blockIdx.x * blockDim.x + threadIdx.x;
    if (idx >= total) return;
    int bc = idx / HW; int r = idx - bc * HW;
    int y = r / W;     int x = r - y * W;
    Xp[((long)bc * (H + 2) + y + 1) * (W + 2) + x + 1] = feat[idx];
}

// ---------------------------------------------------------------------------
// FCOS locations for one level.
// ---------------------------------------------------------------------------
__global__ __launch_bounds__(256) void loc_kernel(
    float* __restrict__ out, int H, int W, int stride, long base)
{
    int idx = blockIdx.x * blockDim.x + threadIdx.x;
    if (idx >= H * W) return;
    int y = idx / W, x = idx - y * W;
    out[base + 2 * idx]     = (float)(x * stride + stride / 2);
    out[base + 2 * idx + 1] = (float)(y * stride + stride / 2);
}

// ---------------------------------------------------------------------------
extern "C" void kernel_launch(void* const* d_in, const int* in_sizes, int n_in,
                              void* d_out, int out_size)
{
    (void)in_sizes; (void)n_in; (void)out_size;
    const float* feats[5];
    for (int i = 0; i < 5; i++) feats[i] = (const float*)d_in[i];
    const float* cls_w    = (const float*)d_in[5];
    const float* cls_b    = (const float*)d_in[6];
    const float* cls_gn_g = (const float*)d_in[7];
    const float* cls_gn_b = (const float*)d_in[8];
    const float* box_w    = (const float*)d_in[9];
    const float* box_b    = (const float*)d_in[10];
    const float* box_gn_g = (const float*)d_in[11];
    const float* box_gn_b = (const float*)d_in[12];
    const float* logits_w = (const float*)d_in[13];
    const float* logits_b = (const float*)d_in[14];
    const float* ctr_w    = (const float*)d_in[15];
    const float* ctr_b    = (const float*)d_in[16];
    const float* reg_w    = (const float*)d_in[17];
    const float* reg_b    = (const float*)d_in[18];
    const float* scales   = (const float*)d_in[19];
    float* out = (float*)d_out;

    float *bufA, *bufB;
    cudaGetSymbolAddress((void**)&bufA, g_bufA);
    cudaGetSymbolAddress((void**)&bufB, g_bufB);

    static const int HS[5]  = {100, 50, 25, 13, 7};
    static const int WS[5]  = {152, 76, 38, 19, 10};
    static const int STR[5] = {8, 16, 32, 64, 128};

    long out_boff = 0;
    for (int l = 0; l < 5; l++) out_boff += 85L * HS[l] * WS[l];  // 1,722,695
    const long locs_base = (long)BATCH * out_boff;                // 13,781,560

    long lvl_off = 0, loc_off = 0;
    for (int l = 0; l < 5; l++) {
        const int H = HS[l], W = WS[l], HW = H * W;
        const int N = BATCH * HW;
        const int total = BATCH * CIN * HW;
        const size_t padbytes = (size_t)BATCH * CIN * (H + 2) * (W + 2) * sizeof(float);

        cudaMemsetAsync(bufA, 0, padbytes);
        cudaMemsetAsync(bufB, 0, padbytes);

        const int eg = (total + 255) / 256;
        const int nx = (N + BN - 1) / BN;
        dim3 gconv(nx, 2);   // M=256 -> 2 tiles of 128
        dim3 g1(nx, 1);      // M<=128

        // ---- cls tower ----
        pad_copy_kernel<<<eg, 256>>>(feats[l], bufA, H, W);
        for (int i = 0; i < 4; i++) {
            conv_gemm_kernel<<<gconv, 256>>>(cls_w + (long)i * CIN * KDIM, cls_b + i * CIN,
                                             bufA, bufB, nullptr, 256, H, W,
                                             0, 0, 0, 0, nullptr, 0, 0);
            gn_stats_kernel<<<256, 256>>>(bufB, H, W);
            gn_apply_relu_kernel<<<eg, 256>>>(bufB, bufA, cls_gn_g + i * CIN,
                                              cls_gn_b + i * CIN, H, W);
        }
        conv_gemm_kernel<<<g1, 256>>>(logits_w, logits_b, bufA, nullptr, out, 80, H, W,
                                      1, out_boff, lvl_off, 0, nullptr, l, 0);
        conv_gemm_kernel<<<g1, 256>>>(ctr_w, ctr_b, bufA, nullptr, out, 1, H, W,
                                      1, out_boff, lvl_off, 84, nullptr, l, 0);

        // ---- box tower ----
        pad_copy_kernel<<<eg, 256>>>(feats[l], bufA, H, W);
        for (int i = 0; i < 4; i++) {
            conv_gemm_kernel<<<gconv, 256>>>(box_w + (long)i * CIN * KDIM, box_b + i * CIN,
                                             bufA, bufB, nullptr, 256, H, W,
                                             0, 0, 0, 0, nullptr, 0, 0);
            gn_stats_kernel<<<256, 256>>>(bufB, H, W);
            gn_apply_relu_kernel<<<eg, 256>>>(bufB, bufA, box_gn_g + i * CIN,
                                              box_gn_b + i * CIN, H, W);
        }
        conv_gemm_kernel<<<g1, 256>>>(reg_w, reg_b, bufA, nullptr, out, 4, H, W,
                                      1, out_boff, lvl_off, 80, scales, l, 1);

        loc_kernel<<<(HW + 255) / 256, 256>>>(out, H, W, STR[l], locs_base + 2 * loc_off);

        lvl_off += 85L * HW;
        loc_off += HW;
    }
}

// round 6
// speedup vs baseline: 3.1465x; 3.1465x over previous
#include <cuda_runtime.h>
#include <cuda_bf16.h>
#include <math.h>
#include <stdint.h>

// ===========================================================================
// FCOS head via mma.sync bf16 tensor cores (compute_100-safe; no tcgen05).
// Conv3x3 as implicit GEMM, bf16 hi/lo 3-term split (AhBh+AhBl+AlBh) ~1e-5.
// Activations in padded NHWC bf16 (hi,lo); weights pre-transposed per launch.
// cp.async double-buffered stages; ldmatrix + mma.sync.m16n8k16.
// ===========================================================================

#define BATCH 8
#define KDIM 2304
#define MAXPADPOS ((size_t)BATCH * 102 * 154)
#define MAXPOS    ((size_t)BATCH * 100 * 152)

// ---------------- device buffers -------------------------------------------
__device__ __align__(16) __nv_bfloat16 g_Xin_h[MAXPADPOS * 256];
__device__ __align__(16) __nv_bfloat16 g_Xin_l[MAXPADPOS * 256];
__device__ __align__(16) __nv_bfloat16 g_Xa_h [MAXPADPOS * 256];
__device__ __align__(16) __nv_bfloat16 g_Xa_l [MAXPADPOS * 256];
__device__ __align__(16) __nv_bfloat16 g_Xb_h [MAXPADPOS * 256];
__device__ __align__(16) __nv_bfloat16 g_Xb_l [MAXPADPOS * 256];
__device__ __align__(16) float g_convout[MAXPOS * 256];
__device__ __align__(16) __nv_bfloat16 g_Wth[8 * 256 * KDIM];
__device__ __align__(16) __nv_bfloat16 g_Wtl[8 * 256 * KDIM];
__device__ __align__(16) __nv_bfloat16 g_Whh[2 * 128 * KDIM];
__device__ __align__(16) __nv_bfloat16 g_Whl[2 * 128 * KDIM];
__device__ float g_hb[2 * 128];
__device__ float g_ps [256 * 32];
__device__ float g_ps2[256 * 32];
__device__ float g_mean[256];
__device__ float g_rstd[256];

__device__ __forceinline__ void bf_split(float v, __nv_bfloat16& h, __nv_bfloat16& l) {
    h = __float2bfloat16(v);
    l = __float2bfloat16(v - __bfloat162float(h));
}

// ---------------- PTX helpers (sm_80-era, compute_100-legal) ----------------
__device__ __forceinline__ uint32_t smem_to_u32(const void* p) {
    uint32_t a;
    asm("{ .reg .u64 t; cvta.to.shared.u64 t, %1; cvt.u32.u64 %0, t; }"
        : "=r"(a) : "l"(p));
    return a;
}
#define CP_ASYNC16(dst, src) \
    asm volatile("cp.async.cg.shared.global [%0], [%1], 16;" \
                 :: "r"(dst), "l"(src))
#define CP_COMMIT() asm volatile("cp.async.commit_group;" ::: "memory")
#define CP_WAIT(n)  asm volatile("cp.async.wait_group %0;" :: "n"(n) : "memory")

__device__ __forceinline__ void ldsm4(uint32_t (&r)[4], uint32_t a) {
    asm volatile("ldmatrix.sync.aligned.m8n8.x4.shared.b16 {%0,%1,%2,%3}, [%4];"
        : "=r"(r[0]), "=r"(r[1]), "=r"(r[2]), "=r"(r[3]) : "r"(a));
}
__device__ __forceinline__ void mma16816(float* d, const uint32_t* a, const uint32_t* b) {
    asm volatile(
        "mma.sync.aligned.m16n8k16.row.col.f32.bf16.bf16.f32 "
        "{%0,%1,%2,%3}, {%4,%5,%6,%7}, {%8,%9}, {%0,%1,%2,%3};"
        : "+f"(d[0]), "+f"(d[1]), "+f"(d[2]), "+f"(d[3])
        : "r"(a[0]), "r"(a[1]), "r"(a[2]), "r"(a[3]), "r"(b[0]), "r"(b[1]));
}

// ---------------- prep kernels ---------------------------------------------
__global__ void prep_weights_kernel(const float* __restrict__ cls_w,
                                    const float* __restrict__ box_w)
{
    long idx = (long)blockIdx.x * blockDim.x + threadIdx.x;
    if (idx >= 8L * 256 * KDIM) return;
    int j = (int)(idx / (256 * KDIM));
    int rem = (int)(idx - (long)j * 256 * KDIM);
    int m = rem / KDIM, k = rem - m * KDIM;
    int tap = k >> 8, ci = k & 255;
    const float* src = (j < 4) ? cls_w + (long)j * 256 * KDIM
                               : box_w + (long)(j - 4) * 256 * KDIM;
    float v = src[(m * 256 + ci) * 9 + tap];
    bf_split(v, g_Wth[idx], g_Wtl[idx]);
}

__global__ void prep_heads_kernel(const float* __restrict__ logits_w,
                                  const float* __restrict__ logits_b,
                                  const float* __restrict__ ctr_w,
                                  const float* __restrict__ ctr_b,
                                  const float* __restrict__ reg_w,
                                  const float* __restrict__ reg_b)
{
    long idx = (long)blockIdx.x * blockDim.x + threadIdx.x;
    if (idx >= 2L * 128 * KDIM) return;
    int which = (int)(idx / (128 * KDIM));
    int rem = (int)(idx - (long)which * 128 * KDIM);
    int m = rem / KDIM, k = rem - m * KDIM;
    int tap = k >> 8, ci = k & 255;
    float v = 0.f;
    if (which == 0) {
        if (m < 80)       v = logits_w[(m * 256 + ci) * 9 + tap];
        else if (m == 80) v = ctr_w[ci * 9 + tap];
    } else {
        if (m < 4) v = reg_w[(m * 256 + ci) * 9 + tap];
    }
    bf_split(v, g_Whh[idx], g_Whl[idx]);
    if (k == 0) {
        float bv = 0.f;
        if (which == 0) { if (m < 80) bv = logits_b[m]; else if (m == 80) bv = ctr_b[0]; }
        else            { if (m < 4)  bv = reg_b[m]; }
        g_hb[which * 128 + m] = bv;
    }
}

__global__ void border_zero_kernel(__nv_bfloat16* bh, __nv_bfloat16* bl, int H, int W)
{
    const int Hp = H + 2, Wp = W + 2;
    const int cnt = 2 * Wp + 2 * H;
    long idx = (long)blockIdx.x * blockDim.x + threadIdx.x;
    if (idx >= (long)BATCH * cnt * 32) return;
    int b = (int)(idx / (cnt * 32));
    int r = (int)(idx - (long)b * cnt * 32);
    int i = r >> 5, q = r & 31;
    int y, x;
    if (i < Wp)              { y = 0;      x = i; }
    else if (i < 2 * Wp)     { y = Hp - 1; x = i - Wp; }
    else if (i < 2 * Wp + H) { y = 1 + (i - 2 * Wp);     x = 0; }
    else                     { y = 1 + (i - 2 * Wp - H); x = Wp - 1; }
    long a = (((long)b * Hp + y) * Wp + x) * 256 + q * 8;
    uint4 z = make_uint4(0, 0, 0, 0);
    *(uint4*)(bh + a) = z;
    *(uint4*)(bl + a) = z;
}

// NCHW f32 feat -> padded NHWC bf16 hi/lo interior.
__global__ void pad_in_kernel(const float* __restrict__ feat,
                              __nv_bfloat16* __restrict__ xh,
                              __nv_bfloat16* __restrict__ xl, int H, int W)
{
    const int HW = H * W;
    long idx = (long)blockIdx.x * blockDim.x + threadIdx.x;
    if (idx >= (long)BATCH * HW * 256) return;
    int c = (int)(idx & 255);
    int p = (int)(idx >> 8);
    int b = p / HW, hw = p - b * HW;
    int y = hw / W, x = hw - y * W;
    float v = feat[((long)(b * 256 + c) * H + y) * W + x];
    long a = (((long)b * (H + 2) + y + 1) * (W + 2) + x + 1) * 256 + c;
    bf_split(v, xh[a], xl[a]);
}

// ---------------- conv via mma.sync ----------------------------------------
// Stage: 4 tiles (Ah, Al, Bh, Bl) of [128 rows][32 halfs], row stride 40 halfs
// (80 bytes: 16B-aligned, conflict-free for ldmatrix). Double buffered.
#define ROWB 80
#define TILE_BYTES (128 * ROWB)          // 10240
#define STAGE_BYTES (4 * TILE_BYTES)     // 40960
#define DYN_SMEM (2 * STAGE_BYTES + 512 + 64)

__global__ __launch_bounds__(256) void conv_mma_kernel(
    const __nv_bfloat16* __restrict__ Wh, const __nv_bfloat16* __restrict__ Wl,
    const float* __restrict__ bias,
    const __nv_bfloat16* __restrict__ Xh, const __nv_bfloat16* __restrict__ Xl,
    float* __restrict__ convout, float* __restrict__ dout,
    const float* __restrict__ scales, int lvl,
    int H, int W, int mode, long out_boff, long lvl_off)
{
    const int Hp = H + 2, Wp = W + 2, HW = H * W;
    const int N = BATCH * HW;
    const int n0 = blockIdx.x * 128;
    const int m0 = blockIdx.y * 128;
    const int tid = threadIdx.x, wid = tid >> 5, lid = tid & 31;

    extern __shared__ char dsm[];
    const uint32_t sb0 = smem_to_u32(dsm);
    int* sbase = (int*)(dsm + 2 * STAGE_BYTES);

    if (tid < 128) {
        int p = n0 + tid;
        if (p >= N) p = N - 1;
        int b = p / HW, hw = p - b * HW;
        int y = hw / W, x = hw - y * W;
        sbase[tid] = ((b * Hp + y) * Wp + x) * 256;
    }
    __syncthreads();

    // Per-thread load channels: 8 cp.async (16B each) per stage.
    const __nv_bfloat16* gbase[8];
    uint32_t sdst[8];
    bool isA[8];
#pragma unroll
    for (int c = 0; c < 8; c++) {
        int id = c * 256 + tid;        // 0..2047
        int tile = id >> 9;            // 0:Ah 1:Al 2:Bh 3:Bl
        int e = id & 511;
        int row = e >> 2, c4 = e & 3;  // 4 x uint4 per row
        isA[c] = (tile < 2);
        if (tile == 0)      gbase[c] = Wh + (long)(m0 + row) * KDIM + c4 * 8;
        else if (tile == 1) gbase[c] = Wl + (long)(m0 + row) * KDIM + c4 * 8;
        else if (tile == 2) gbase[c] = Xh + (long)sbase[row] + c4 * 8;
        else                gbase[c] = Xl + (long)sbase[row] + c4 * 8;
        sdst[c] = sb0 + tile * TILE_BYTES + row * ROWB + c4 * 16;
    }

    const int NSTAGE = KDIM / 32;      // 72
    const int wm = wid & 3, wn = wid >> 2;

    float acc[2][8][4];
#pragma unroll
    for (int i = 0; i < 2; i++)
#pragma unroll
        for (int j = 0; j < 8; j++)
#pragma unroll
            for (int k = 0; k < 4; k++) acc[i][j][k] = 0.f;

    // Issue stage s into buffer s&1.
    auto issue = [&](int s) {
        const uint32_t boff = (uint32_t)(s & 1) * STAGE_BYTES;
        const int kA = s * 32;
        const int tap = s >> 3;
        const int kB = ((tap / 3) * Wp + (tap % 3)) * 256 + (s & 7) * 32;
#pragma unroll
        for (int c = 0; c < 8; c++)
            CP_ASYNC16(sdst[c] + boff, gbase[c] + (isA[c] ? kA : kB));
        CP_COMMIT();
    };

    issue(0);
    for (int s = 0; s < NSTAGE; s++) {
        if (s + 1 < NSTAGE) { issue(s + 1); CP_WAIT(1); }
        else                { CP_WAIT(0); }
        __syncthreads();

        const uint32_t tb = sb0 + (uint32_t)(s & 1) * STAGE_BYTES;
        const uint32_t Ahb = tb, Alb = tb + TILE_BYTES;
        const uint32_t Bhb = tb + 2 * TILE_BYTES, Blb = tb + 3 * TILE_BYTES;

#pragma unroll
        for (int sl = 0; sl < 2; sl++) {
            uint32_t ah[2][4], al[2][4];
#pragma unroll
            for (int mi = 0; mi < 2; mi++) {
                uint32_t ao = (uint32_t)((wm * 32 + mi * 16 + (lid & 15)) * ROWB
                                         + (sl * 16 + (lid >> 4) * 8) * 2);
                ldsm4(ah[mi], Ahb + ao);
                ldsm4(al[mi], Alb + ao);
            }
#pragma unroll
            for (int ng = 0; ng < 4; ng++) {
                const int q = lid >> 3;
                uint32_t bo = (uint32_t)((wn * 64 + ng * 16 + (q >> 1) * 8 + (lid & 7)) * ROWB
                                         + (sl * 16 + (q & 1) * 8) * 2);
                uint32_t bh[4], bl[4];
                ldsm4(bh, Bhb + bo);
                ldsm4(bl, Blb + bo);
#pragma unroll
                for (int mi = 0; mi < 2; mi++) {
#pragma unroll
                    for (int h = 0; h < 2; h++) {
                        float* d = acc[mi][ng * 2 + h];
                        mma16816(d, ah[mi], &bh[h * 2]);
                        mma16816(d, ah[mi], &bl[h * 2]);
                        mma16816(d, al[mi], &bh[h * 2]);
                    }
                }
            }
        }
        __syncthreads();
    }

    // Epilogue.
    const float sc = (mode == 2) ? scales[lvl] : 0.f;
#pragma unroll
    for (int mi = 0; mi < 2; mi++) {
        const int mlo = m0 + wm * 32 + mi * 16 + (lid >> 2);
        const float bv0 = bias[mlo - m0 + m0];  // bias indexed by global m
        const float bv1 = bias[mlo + 8];
#pragma unroll
        for (int ng = 0; ng < 4; ng++) {
#pragma unroll
            for (int h = 0; h < 2; h++) {
                const float* d = acc[mi][ng * 2 + h];
                const int n = n0 + wn * 64 + ng * 16 + h * 8 + 2 * (lid & 3);
#pragma unroll
                for (int e = 0; e < 4; e++) {
                    const int p = n + (e & 1);
                    const int m = (e < 2) ? mlo : mlo + 8;
                    if (p >= N) continue;
                    float v = d[e] + ((e < 2) ? bv0 : bv1);
                    if (mode == 0) {
                        convout[(size_t)p * 256 + m] = v;
                    } else {
                        int b = p / HW, hw = p - b * HW;
                        long ob = (long)b * out_boff + lvl_off;
                        if (mode == 1) {
                            if (m < 80)       dout[ob + (long)m * HW + hw] = v;
                            else if (m == 80) dout[ob + 84L * HW + hw] = v;
                        } else {
                            if (m < 4) dout[ob + (long)(80 + m) * HW + hw] = expf(sc * v);
                        }
                    }
                }
            }
        }
    }
}

// ---------------- GroupNorm (deterministic two-stage) -----------------------
#define GN_CH 32
__global__ __launch_bounds__(256) void gn_stats1_kernel(
    const float* __restrict__ co, int HW)
{
    const int bg = blockIdx.x >> 5;       // 0..255 = b*32+g
    const int ch = blockIdx.x & 31;
    const int b = bg >> 5, g = bg & 31;
    const int len = (HW + GN_CH - 1) / GN_CH;
    const int lo = ch * len;
    const int hi = (lo + len < HW) ? lo + len : HW;
    const long p0 = (long)b * HW;
    float s = 0.f, s2 = 0.f;
    for (int hw = lo + threadIdx.x; hw < hi; hw += 256) {
        const float* r = co + (p0 + hw) * 256 + g * 8;
        float4 a = *(const float4*)r;
        float4 c = *(const float4*)(r + 4);
        s  += a.x + a.y + a.z + a.w + c.x + c.y + c.z + c.w;
        s2 += a.x*a.x + a.y*a.y + a.z*a.z + a.w*a.w
            + c.x*c.x + c.y*c.y + c.z*c.z + c.w*c.w;
    }
    __shared__ float ss[256], ss2[256];
    ss[threadIdx.x] = s; ss2[threadIdx.x] = s2;
    __syncthreads();
    for (int o = 128; o > 0; o >>= 1) {
        if (threadIdx.x < o) {
            ss[threadIdx.x]  += ss[threadIdx.x + o];
            ss2[threadIdx.x] += ss2[threadIdx.x + o];
        }
        __syncthreads();
    }
    if (threadIdx.x == 0) {
        g_ps [bg * 32 + ch] = ss[0];
        g_ps2[bg * 32 + ch] = ss2[0];
    }
}

__global__ void gn_stats2_kernel(int HW)
{
    const int bg = threadIdx.x;   // 256 threads
    float s = 0.f, s2 = 0.f;
    for (int c = 0; c < 32; c++) { s += g_ps[bg * 32 + c]; s2 += g_ps2[bg * 32 + c]; }
    float cnt = 8.f * HW;
    float mean = s / cnt;
    float var  = s2 / cnt - mean * mean;
    g_mean[bg] = mean;
    g_rstd[bg] = rsqrtf(var + 1e-5f);
}

__global__ __launch_bounds__(256) void gn_apply_kernel(
    const float* __restrict__ co,
    __nv_bfloat16* __restrict__ xh, __nv_bfloat16* __restrict__ xl,
    const float* __restrict__ gamma, const float* __restrict__ beta,
    int H, int W)
{
    const int HW = H * W;
    long idx = (long)blockIdx.x * blockDim.x + threadIdx.x;
    if (idx >= (long)BATCH * HW * 256) return;
    int c = (int)(idx & 255);
    int p = (int)(idx >> 8);
    int b = p / HW, hw = p - b * HW;
    int y = hw / W, x = hw - y * W;
    int bg = b * 32 + (c >> 3);
    float v = (co[idx] - g_mean[bg]) * g_rstd[bg] * gamma[c] + beta[c];
    v = v > 0.f ? v : 0.f;
    long a = (((long)b * (H + 2) + y + 1) * (W + 2) + x + 1) * 256 + c;
    bf_split(v, xh[a], xl[a]);
}

__global__ __launch_bounds__(256) void loc_kernel(
    float* __restrict__ out, int H, int W, int stride, long base)
{
    int idx = blockIdx.x * blockDim.x + threadIdx.x;
    if (idx >= H * W) return;
    int y = idx / W, x = idx - y * W;
    out[base + 2 * idx]     = (float)(x * stride + stride / 2);
    out[base + 2 * idx + 1] = (float)(y * stride + stride / 2);
}

// ---------------------------------------------------------------------------
extern "C" void kernel_launch(void* const* d_in, const int* in_sizes, int n_in,
                              void* d_out, int out_size)
{
    (void)in_sizes; (void)n_in; (void)out_size;
    const float* feats[5];
    for (int i = 0; i < 5; i++) feats[i] = (const float*)d_in[i];
    const float* cls_w    = (const float*)d_in[5];
    const float* cls_b    = (const float*)d_in[6];
    const float* cls_gn_g = (const float*)d_in[7];
    const float* cls_gn_b = (const float*)d_in[8];
    const float* box_w    = (const float*)d_in[9];
    const float* box_b    = (const float*)d_in[10];
    const float* box_gn_g = (const float*)d_in[11];
    const float* box_gn_b = (const float*)d_in[12];
    const float* logits_w = (const float*)d_in[13];
    const float* logits_b = (const float*)d_in[14];
    const float* ctr_w    = (const float*)d_in[15];
    const float* ctr_b    = (const float*)d_in[16];
    const float* reg_w    = (const float*)d_in[17];
    const float* reg_b    = (const float*)d_in[18];
    const float* scales   = (const float*)d_in[19];
    float* out = (float*)d_out;

    cudaFuncSetAttribute(conv_mma_kernel,
                         cudaFuncAttributeMaxDynamicSharedMemorySize, DYN_SMEM);

    __nv_bfloat16 *Xin_h, *Xin_l, *Xa_h, *Xa_l, *Xb_h, *Xb_l;
    __nv_bfloat16 *Wth, *Wtl, *Whh, *Whl;
    float *convout, *hb;
    cudaGetSymbolAddress((void**)&Xin_h, g_Xin_h);
    cudaGetSymbolAddress((void**)&Xin_l, g_Xin_l);
    cudaGetSymbolAddress((void**)&Xa_h, g_Xa_h);
    cudaGetSymbolAddress((void**)&Xa_l, g_Xa_l);
    cudaGetSymbolAddress((void**)&Xb_h, g_Xb_h);
    cudaGetSymbolAddress((void**)&Xb_l, g_Xb_l);
    cudaGetSymbolAddress((void**)&Wth, g_Wth);
    cudaGetSymbolAddress((void**)&Wtl, g_Wtl);
    cudaGetSymbolAddress((void**)&Whh, g_Whh);
    cudaGetSymbolAddress((void**)&Whl, g_Whl);
    cudaGetSymbolAddress((void**)&convout, g_convout);
    cudaGetSymbolAddress((void**)&hb, g_hb);

    prep_weights_kernel<<<(int)((8L * 256 * KDIM + 255) / 256), 256>>>(cls_w, box_w);
    prep_heads_kernel<<<(int)((2L * 128 * KDIM + 255) / 256), 256>>>(
        logits_w, logits_b, ctr_w, ctr_b, reg_w, reg_b);

    static const int HS[5]  = {100, 50, 25, 13, 7};
    static const int WS[5]  = {152, 76, 38, 19, 10};
    static const int STR[5] = {8, 16, 32, 64, 128};

    long out_boff = 0;
    for (int l = 0; l < 5; l++) out_boff += 85L * HS[l] * WS[l];
    const long locs_base = (long)BATCH * out_boff;

    long lvl_off = 0, loc_off = 0;
    for (int l = 0; l < 5; l++) {
        const int H = HS[l], W = WS[l], HW = H * W;
        const int N = BATCH * HW;
        const int nblk = (N + 127) / 128;
        const long tot = (long)N * 256;
        const int eg = (int)((tot + 255) / 256);
        const int Hp = H + 2, Wp = W + 2;
        const int bcnt = 2 * Wp + 2 * H;
        const int bg = (int)(((long)BATCH * bcnt * 32 + 255) / 256);

        border_zero_kernel<<<bg, 256>>>(Xin_h, Xin_l, H, W);
        border_zero_kernel<<<bg, 256>>>(Xa_h, Xa_l, H, W);
        border_zero_kernel<<<bg, 256>>>(Xb_h, Xb_l, H, W);
        pad_in_kernel<<<eg, 256>>>(feats[l], Xin_h, Xin_l, H, W);

        __nv_bfloat16* srcs_h[4] = {Xin_h, Xa_h, Xb_h, Xa_h};
        __nv_bfloat16* srcs_l[4] = {Xin_l, Xa_l, Xb_l, Xa_l};
        __nv_bfloat16* dsts_h[4] = {Xa_h, Xb_h, Xa_h, Xb_h};
        __nv_bfloat16* dsts_l[4] = {Xa_l, Xb_l, Xa_l, Xb_l};

        dim3 gconv(nblk, 2);   // towers: M=256 -> 2 m-tiles
        dim3 ghead(nblk, 1);   // heads: M=128

        for (int tower = 0; tower < 2; tower++) {
            const __nv_bfloat16* wtower_h = Wth + (long)tower * 4 * 256 * KDIM;
            const __nv_bfloat16* wtower_l = Wtl + (long)tower * 4 * 256 * KDIM;
            const float* btower = tower ? box_b : cls_b;
            const float* gg = tower ? box_gn_g : cls_gn_g;
            const float* gb = tower ? box_gn_b : cls_gn_b;
            for (int i = 0; i < 4; i++) {
                conv_mma_kernel<<<gconv, 256, DYN_SMEM>>>(
                    wtower_h + (long)i * 256 * KDIM, wtower_l + (long)i * 256 * KDIM,
                    btower + i * 256, srcs_h[i], srcs_l[i],
                    convout, nullptr, scales, l, H, W, 0, 0, 0);
                gn_stats1_kernel<<<256 * GN_CH, 256>>>(convout, HW);
                gn_stats2_kernel<<<1, 256>>>(HW);
                gn_apply_kernel<<<eg, 256>>>(convout, dsts_h[i], dsts_l[i],
                                             gg + i * 256, gb + i * 256, H, W);
            }
            if (tower == 0) {
                conv_mma_kernel<<<ghead, 256, DYN_SMEM>>>(
                    Whh, Whl, hb, Xb_h, Xb_l, nullptr, out, scales, l,
                    H, W, 1, out_boff, lvl_off);
            } else {
                conv_mma_kernel<<<ghead, 256, DYN_SMEM>>>(
                    Whh + (long)128 * KDIM, Whl + (long)128 * KDIM, hb + 128,
                    Xb_h, Xb_l, nullptr, out, scales, l,
                    H, W, 2, out_boff, lvl_off);
            }
        }
        loc_kernel<<<(HW + 255) / 256, 256>>>(out, H, W, STR[l], locs_base + 2 * loc_off);

        lvl_off += 85L * HW;
        loc_off += HW;
    }
}